// round 3
// baseline (speedup 1.0000x reference)
#include <cuda_runtime.h>

// ---------------------------------------------------------------------------
// PrecisionPredictorLoss — single fused kernel.
//   eff  = mean((P - T)^2)                 over B*d*d elements
//   tr_p[b], tr_t[b] = trace of first m=min(B,32) matrices (d=64)
//   rank = sum_{i<j} margin(tr) / (m*(m-1)/2)
//   total = eff + 0.1 * rank
// Shapes fixed by problem: B=4096, d=64.
//
// NBLK streaming blocks + 1 trace block. Last block to finish (integer ticket)
// performs the finalize on L2-hot partials. Counter is reset by the last block
// so replay under CUDA graph is deterministic.
// ---------------------------------------------------------------------------

#define NBLK 1184          // 148 SMs * 8 streaming blocks
#define TPB  256
#define NTOT (NBLK + 1)

__device__ float g_partials[NBLK];
__device__ float g_tr_p[32];
__device__ float g_tr_t[32];
__device__ unsigned int g_ticket = 0;   // statically zero; reset each run

__device__ __forceinline__ float warp_sum(float v) {
    #pragma unroll
    for (int o = 16; o; o >>= 1) v += __shfl_down_sync(0xffffffffu, v, o);
    return v;
}

__global__ void __launch_bounds__(TPB) fused_loss(
    const float4* __restrict__ p, const float4* __restrict__ t,
    float* __restrict__ out, int n4, int B, long long n_total, int out_size)
{
    __shared__ float s[TPB / 32];
    __shared__ bool s_last;

    const int tid  = threadIdx.x;
    const int warp = tid >> 5;
    const int lane = tid & 31;
    const int m    = (B < 32) ? B : 32;

    if (blockIdx.x == NBLK) {
        // ---- trace block: 8 warps x 4 matrices each ----
        const float* pf = (const float*)p;
        const float* tf = (const float*)t;
        #pragma unroll
        for (int k = 0; k < 4; k++) {
            int b = warp * 4 + k;
            if (b >= m) break;
            const long long base = (long long)b * 64 * 64;
            float tp = pf[base + (long long)lane * 65]
                     + pf[base + (long long)(lane + 32) * 65];
            float tt = tf[base + (long long)lane * 65]
                     + tf[base + (long long)(lane + 32) * 65];
            tp = warp_sum(tp);
            tt = warp_sum(tt);
            if (lane == 0) { g_tr_p[b] = tp; g_tr_t[b] = tt; }
        }
    } else {
        // ---- streaming squared-diff partial reduction ----
        float acc = 0.0f;
        const int stride = NBLK * TPB;
        #pragma unroll 4
        for (int i = blockIdx.x * TPB + tid; i < n4; i += stride) {
            float4 a = p[i];
            float4 b = t[i];
            float d0 = a.x - b.x, d1 = a.y - b.y, d2 = a.z - b.z, d3 = a.w - b.w;
            acc = fmaf(d0, d0, acc);
            acc = fmaf(d1, d1, acc);
            acc = fmaf(d2, d2, acc);
            acc = fmaf(d3, d3, acc);
        }
        acc = warp_sum(acc);
        if (lane == 0) s[warp] = acc;
        __syncthreads();
        if (tid < 32) {
            float v = (tid < TPB / 32) ? s[tid] : 0.0f;
            #pragma unroll
            for (int o = 4; o; o >>= 1) v += __shfl_down_sync(0xffffffffu, v, o);
            if (tid == 0) g_partials[blockIdx.x] = v;
        }
    }

    // ---- ticket: last block to arrive performs the finalize ----
    __threadfence();
    if (tid == 0) {
        unsigned int ticket = atomicAdd(&g_ticket, 1u);
        s_last = (ticket == NTOT - 1);
    }
    __syncthreads();
    if (!s_last) return;

    // =========================== FINALIZE (one block) =======================
    // 1) reduce NBLK partials (L2-hot)
    float sum = 0.0f;
    for (int i = tid; i < NBLK; i += TPB) sum += g_partials[i];
    sum = warp_sum(sum);
    if (lane == 0) s[warp] = sum;
    __syncthreads();
    float sumsq = 0.0f;
    if (tid == 0) {
        #pragma unroll
        for (int i = 0; i < TPB / 32; i++) sumsq += s[i];
    }
    __syncthreads();   // s[] reuse below

    // 2) rank loss: 1024 (i,j) slots over 256 threads, 4 slots each
    float c = 0.0f;
    #pragma unroll
    for (int sIdx = 0; sIdx < 4; sIdx++) {
        int idx = tid + TPB * sIdx;     // 0..1023
        int i = idx >> 5;
        int j = idx & 31;
        if (i < j && j < m) {
            float dt = g_tr_t[i] - g_tr_t[j];
            float dp = g_tr_p[i] - g_tr_p[j];
            if (dt > 0.0f)      c += fmaxf(-dp + 0.1f, 0.0f);
            else if (dt < 0.0f) c += fmaxf( dp + 0.1f, 0.0f);
        }
    }
    c = warp_sum(c);
    if (lane == 0) s[warp] = c;
    __syncthreads();

    // 3) combine, write outputs, reset ticket for next graph replay
    if (tid == 0) {
        float rank_total = 0.0f;
        #pragma unroll
        for (int i = 0; i < TPB / 32; i++) rank_total += s[i];
        float eff = sumsq / (float)n_total;
        int n_pairs = m * (m - 1) / 2;
        float rank = (m > 1) ? (rank_total / (float)n_pairs) : 0.0f;
        out[0] = eff + 0.1f * rank;
        if (out_size > 1) out[1] = eff;
        if (out_size > 2) out[2] = rank;
        __threadfence();
        g_ticket = 0;                  // deterministic replay
    }
}

extern "C" void kernel_launch(void* const* d_in, const int* in_sizes, int n_in,
                              void* d_out, int out_size)
{
    const float* pred = (const float*)d_in[0];
    const float* tru  = (const float*)d_in[1];
    float* out = (float*)d_out;

    long long n = (long long)in_sizes[0];   // B * 64 * 64
    int n4 = (int)(n / 4);
    int B  = (int)(n / (64 * 64));

    fused_loss<<<NTOT, TPB>>>((const float4*)pred, (const float4*)tru,
                              out, n4, B, n, out_size);
}

// round 4
// speedup vs baseline: 1.0849x; 1.0849x over previous
#include <cuda_runtime.h>

// ---------------------------------------------------------------------------
// PrecisionPredictorLoss — two kernels, finalize overlapped via PDL.
//   eff  = mean((P - T)^2)                 over B*d*d elements
//   tr_p[b], tr_t[b] = trace of first m=min(B,32) matrices (d=64)
//   rank = sum_{i<j} margin(tr) / (m*(m-1)/2)
//   total = eff + 0.1 * rank
// Shapes fixed by problem: B=4096, d=64.
//
// Kernel 1: NBLK streaming blocks + 1 trace block (overlapped).
// Kernel 2: grid=1 finalize, launched with programmatic dependent launch so
// its launch/ramp overhead hides under kernel 1's 21us streaming wave; it
// waits at cudaGridDependencySynchronize() for kernel 1's memory to land.
// ---------------------------------------------------------------------------

#define NBLK 1184          // 148 SMs * 8 streaming blocks
#define TPB  256

__device__ float g_partials[NBLK];
__device__ float g_tr_p[32];
__device__ float g_tr_t[32];

__device__ __forceinline__ float warp_sum(float v) {
    #pragma unroll
    for (int o = 16; o; o >>= 1) v += __shfl_down_sync(0xffffffffu, v, o);
    return v;
}

__global__ void __launch_bounds__(TPB) main_pass(
    const float4* __restrict__ p, const float4* __restrict__ t,
    int n4, int B)
{
    if (blockIdx.x == NBLK) {
        // ---- trace block: 8 warps, each handles 4 of the first m matrices ----
        const float* pf = (const float*)p;
        const float* tf = (const float*)t;
        const int warp = threadIdx.x >> 5;
        const int lane = threadIdx.x & 31;
        const int m = (B < 32) ? B : 32;
        #pragma unroll
        for (int k = 0; k < 4; k++) {
            int b = warp * 4 + k;              // matrix index 0..31
            if (b >= m) break;
            const long long base = (long long)b * 64 * 64;
            float tp = pf[base + (long long)lane * 65]
                     + pf[base + (long long)(lane + 32) * 65];
            float tt = tf[base + (long long)lane * 65]
                     + tf[base + (long long)(lane + 32) * 65];
            tp = warp_sum(tp);
            tt = warp_sum(tt);
            if (lane == 0) { g_tr_p[b] = tp; g_tr_t[b] = tt; }
        }
        return;
    }

    // ---- streaming squared-diff partial reduction ----
    float acc = 0.0f;
    const int stride = NBLK * TPB;
    #pragma unroll 4
    for (int i = blockIdx.x * TPB + threadIdx.x; i < n4; i += stride) {
        float4 a = p[i];
        float4 b = t[i];
        float d0 = a.x - b.x, d1 = a.y - b.y, d2 = a.z - b.z, d3 = a.w - b.w;
        acc = fmaf(d0, d0, acc);
        acc = fmaf(d1, d1, acc);
        acc = fmaf(d2, d2, acc);
        acc = fmaf(d3, d3, acc);
    }
    __shared__ float s[TPB / 32];
    acc = warp_sum(acc);
    if ((threadIdx.x & 31) == 0) s[threadIdx.x >> 5] = acc;
    __syncthreads();
    if (threadIdx.x < 32) {
        float v = (threadIdx.x < TPB / 32) ? s[threadIdx.x] : 0.0f;
        #pragma unroll
        for (int o = 4; o; o >>= 1) v += __shfl_down_sync(0xffffffffu, v, o);
        if (threadIdx.x == 0) g_partials[blockIdx.x] = v;
    }
}

__global__ void __launch_bounds__(1024) finalize_kernel(
    float* __restrict__ out, long long n_total, int B, int out_size)
{
    // PDL: we may have been launched while main_pass is still running.
    // Block here until main_pass's grid (and its memory) is complete.
    cudaGridDependencySynchronize();

    __shared__ float red[32];
    __shared__ float s_sumsq;

    const int tid  = threadIdx.x;
    const int warp = tid >> 5;
    const int lane = tid & 31;
    const int m    = (B < 32) ? B : 32;

    // ---- 1) reduce the NBLK per-block partials (L2-resident) ----
    float s = 0.0f;
    for (int i = tid; i < NBLK; i += 1024) s += g_partials[i];
    s = warp_sum(s);
    if (lane == 0) red[warp] = s;
    __syncthreads();
    if (tid < 32) {
        float v = red[tid];
        #pragma unroll
        for (int o = 16; o; o >>= 1) v += __shfl_down_sync(0xffffffffu, v, o);
        if (tid == 0) s_sumsq = v;
    }
    __syncthreads();

    // ---- 2) pairwise rank loss over upper triangle (i < j), warp=i lane=j ----
    float c = 0.0f;
    if (warp < m && lane < m && warp < lane) {
        float dt = g_tr_t[warp] - g_tr_t[lane];
        float dp = g_tr_p[warp] - g_tr_p[lane];
        if (dt > 0.0f)      c = fmaxf(-dp + 0.1f, 0.0f);
        else if (dt < 0.0f) c = fmaxf( dp + 0.1f, 0.0f);
    }
    c = warp_sum(c);
    if (lane == 0) red[warp] = c;
    __syncthreads();

    // ---- 3) combine and write outputs ----
    if (tid == 0) {
        float rank_total = 0.0f;
        #pragma unroll
        for (int i = 0; i < 32; i++) rank_total += red[i];
        float eff = s_sumsq / (float)n_total;
        int n_pairs = m * (m - 1) / 2;
        float rank = (m > 1) ? (rank_total / (float)n_pairs) : 0.0f;
        out[0] = eff + 0.1f * rank;
        if (out_size > 1) out[1] = eff;
        if (out_size > 2) out[2] = rank;
    }
}

extern "C" void kernel_launch(void* const* d_in, const int* in_sizes, int n_in,
                              void* d_out, int out_size)
{
    const float* pred = (const float*)d_in[0];
    const float* tru  = (const float*)d_in[1];
    float* out = (float*)d_out;

    long long n = (long long)in_sizes[0];   // B * 64 * 64
    int n4 = (int)(n / 4);
    int B  = (int)(n / (64 * 64));

    main_pass<<<NBLK + 1, TPB>>>((const float4*)pred, (const float4*)tru, n4, B);

    // Finalize with programmatic dependent launch: overlap its launch/ramp
    // with main_pass execution; it self-synchronizes via
    // cudaGridDependencySynchronize().
    cudaLaunchConfig_t cfg = {};
    cfg.gridDim  = dim3(1, 1, 1);
    cfg.blockDim = dim3(1024, 1, 1);
    cfg.dynamicSmemBytes = 0;
    cfg.stream = 0;
    cudaLaunchAttribute attr[1];
    attr[0].id = cudaLaunchAttributeProgrammaticStreamSerialization;
    attr[0].val.programmaticStreamSerializationAllowed = 1;
    cfg.attrs = attr;
    cfg.numAttrs = 1;
    cudaError_t e = cudaLaunchKernelEx(&cfg, finalize_kernel, out, n, B, out_size);
    if (e != cudaSuccess) {
        // Fallback: plain launch (still correct, just serialized).
        finalize_kernel<<<1, 1024>>>(out, n, B, out_size);
    }
}